// round 2
// baseline (speedup 1.0000x reference)
#include <cuda_runtime.h>
#include <cuda_bf16.h>

// Problem constants (fixed for ReconModelMP_17549236371725)
#define BATCH   8
#define NVERTS  468
#define NTRI    256
#define IMG     1024

// Per-(batch,triangle) edge data: 3 edges x (dx, dy, ox, oy) = 12 floats.
// Edge function (matching the jax reference exactly):
//   w = dx*(py - oy) - dy*(px - ox)
// edge0: (b -> c), edge1: (c -> a), edge2: (a -> b)
__device__ float g_coef[BATCH * NTRI * 12];

__global__ void prep_kernel(const float* __restrict__ lm,
                            const int* __restrict__ tri) {
    const int b = blockIdx.x;      // batch
    const int t = threadIdx.x;     // triangle (256 threads)

    const int i0 = tri[t * 3 + 0];
    const int i1 = tri[t * 3 + 1];
    const int i2 = tri[t * 3 + 2];

    const float* base = lm + (size_t)b * NVERTS * 3;
    const float ax = base[i0 * 3 + 0], ay = base[i0 * 3 + 1];
    const float bx = base[i1 * 3 + 0], by = base[i1 * 3 + 1];
    const float cx = base[i2 * 3 + 0], cy = base[i2 * 3 + 1];

    float* o = g_coef + ((size_t)b * NTRI + t) * 12;
    // edge0: edge(b, c) = (cx-bx)*(py-by) - (cy-by)*(px-bx)
    o[0]  = cx - bx;  o[1]  = cy - by;  o[2]  = bx;  o[3]  = by;
    // edge1: edge(c, a) = (ax-cx)*(py-cy) - (ay-cy)*(px-cx)
    o[4]  = ax - cx;  o[5]  = ay - cy;  o[6]  = cx;  o[7]  = cy;
    // edge2: edge(a, b) = (bx-ax)*(py-ay) - (by-ay)*(px-ax)
    o[8]  = bx - ax;  o[9]  = by - ay;  o[10] = ax;  o[11] = ay;
}

// Tile = 32 (x) x 8 (y) pixels. 256 threads, 1 pixel/thread.
// Warp = one 32-pixel row -> coalesced 128B float stores and a spatially
// coherent __all_sync early-exit.
__global__ __launch_bounds__(256)
void rast_kernel(float* __restrict__ out) {
    __shared__ float4 sc[NTRI * 3];   // 12 KB

    const int b = blockIdx.z;
    // Stage this batch's edge data into smem (coalesced float4 loads).
    const float4* g = reinterpret_cast<const float4*>(g_coef + (size_t)b * NTRI * 12);
    for (int i = threadIdx.x; i < NTRI * 3; i += 256) sc[i] = g[i];
    __syncthreads();

    const int x = blockIdx.x * 32 + (threadIdx.x & 31);
    const int y = blockIdx.y * 8  + (threadIdx.x >> 5);

    // Orthographic camera flips both axes: p = 1 - (idx + 0.5)/S
    const float px = 1.0f - ((float)x + 0.5f) * (1.0f / (float)IMG);
    const float py = 1.0f - ((float)y + 0.5f) * (1.0f / (float)IMG);

    bool covered = false;

    #pragma unroll 1
    for (int t = 0; t < NTRI; ++t) {
        const float4 e0 = sc[t * 3 + 0];  // dx0, dy0, ox0, oy0
        const float4 e1 = sc[t * 3 + 1];
        const float4 e2 = sc[t * 3 + 2];

        // w = dx*(py-oy) - dy*(px-ox), contracted as fma(dx, py-oy, -(dy*(px-ox)))
        const float w0 = fmaf(e0.x, py - e0.w, -(e0.y * (px - e0.z)));
        const float w1 = fmaf(e1.x, py - e1.w, -(e1.y * (px - e1.z)));
        const float w2 = fmaf(e2.x, py - e2.w, -(e2.y * (px - e2.z)));

        const float mn = fminf(w0, fminf(w1, w2));
        const float mx = fmaxf(w0, fmaxf(w1, w2));
        covered = covered || (mn >= 0.0f) || (mx <= 0.0f);

        // Warp-coherent early exit: once every lane in this row is covered,
        // remaining triangles cannot change the result.
        if (__all_sync(0xffffffffu, covered)) break;
    }

    out[((size_t)b << 20) + (size_t)y * IMG + x] = covered ? 1.0f : 0.0f;
}

extern "C" void kernel_launch(void* const* d_in, const int* in_sizes, int n_in,
                              void* d_out, int out_size) {
    const float* landmarks = (const float*)d_in[0];   // [8, 468, 3] f32
    const int*   tri       = (const int*)d_in[1];     // [256, 3] i32
    // d_in[2] = img_size (fixed 1024, compiled in)
    float* out = (float*)d_out;                       // [8, 1024, 1024] bool -> f32

    prep_kernel<<<BATCH, NTRI>>>(landmarks, tri);

    dim3 grid(IMG / 32, IMG / 8, BATCH);
    rast_kernel<<<grid, 256>>>(out);
}